// round 10
// baseline (speedup 1.0000x reference)
#include <cuda_runtime.h>

// ---------------------------------------------------------------------------
// B=64, S=1024, H=256, NF=C=256, K=7, POOL=3, layer==1 (no pad).
// Inputs: 0 x[64,1024,256] 1 layer 2 gk_f[256,768] 3 gr_f[256,768] 4 gb_f[2,768]
//         5 gk_b 6 gr_b 7 gb_b 8 Wa[512,65536] 9 Wb[256,1792] 10 conv_bias[256]
// Output: [64, 341, 256] f32
//
// Conv restructured:  y[b][s][n] = sum_e a[b][n][e] * Z[b][s][e],
//   Z[b][s][e] = sum_{k,m} x[b][s+k-3][m] * Wb[e][m*7+k]   (static conv)
// GRU: 128 persistent blocks = dir(2) x bgroup(4, 16 batches) x ugroup(16, 16 units),
//   island barriers (16 blocks each) instead of one global barrier.
// ---------------------------------------------------------------------------

static constexpr int Bn = 64, Sn = 1024, Hn = 256, NFn = 256, Kn = 7;

// -------------------- static device scratch --------------------------------
__device__ float    g_xT[Sn * Bn * 256];          //  67 MB  [s][b][c]
__device__ float    g_xp[2][Sn * Bn * 768];       // 403 MB  [dir][s*64+b][768]
__device__ float    g_h[2][2][Bn * Hn];           //         [dir][pp][b][h]
__device__ float    g_Bz[Kn * 256 * 256];         // 1.8 MB  [k*256+m][e]
__device__ float    g_Z[Sn * Bn * 256];           //  67 MB  [s*64+b][e]
__device__ float    g_aT[Bn * 256 * 256];         //  17 MB  [b][e][n]
__device__ float    g_y[Bn * Sn * NFn];           //  67 MB  [b][s][n]
__device__ unsigned g_arr2[8][32];                // island counters, 128B apart

// ---------------------------------------------------------------------------
__global__ void transpose_kernel(const float* __restrict__ x)
{
    int s = blockIdx.x, b = blockIdx.y;
    int c4 = threadIdx.x;
    float4 v = ((const float4*)(x + (b * Sn + s) * 256))[c4];
    ((float4*)(g_xT + (s * Bn + b) * 256))[c4] = v;
}

// ---------------------------------------------------------------------------
// reset island counters + zero h state (every launch -> graph-replay safe)
// ---------------------------------------------------------------------------
__global__ void reset_kernel()
{
    int i = blockIdx.x * blockDim.x + threadIdx.x;
    if (i < 8) g_arr2[i][0] = 0u;
    ((float*)g_h)[i] = 0.f;                       // 2*2*64*256 = 65536
}

// ---------------------------------------------------------------------------
// Bz[(k*256+m)][e] = Wb[e][m*7+k]
// ---------------------------------------------------------------------------
__global__ void prep_bz_kernel(const float* __restrict__ Wb)
{
    int j = blockIdx.x;                 // 0..1791
    int e = threadIdx.x;                // 0..255
    int k = j >> 8, m = j & 255;
    g_Bz[j * 256 + e] = Wb[e * 1792 + m * 7 + k];
}

// ---------------------------------------------------------------------------
// 128x128-tile SGEMM, 256 threads, 8x8/thread, BK=16, double-buffered smem.
// MODE 0: xp = xT @ Wk + bias.   K=256, LDB=768. grid(512,6)
// MODE 1: Z = im2col(xT) @ Bz.   K=1792, LDB=256. grid(512,2)
// MODE 2: y[b] = Z[:,b,:] @ aT[b]. K=256, LDB=256. grid(8,2,64)
// ---------------------------------------------------------------------------
template <int MODE>
__global__ __launch_bounds__(256, 2) void gemm128(const float* __restrict__ Bmat,
                                                  const float* __restrict__ bias,
                                                  int dir)
{
    constexpr int KDIM = (MODE == 1) ? 1792 : 256;
    constexpr int LDB  = (MODE == 0) ? 768 : 256;
    constexpr int NT   = KDIM / 16;

    __shared__ float As[2][16][132];
    __shared__ float Bs[2][16][128];

    const int tid     = threadIdx.x;
    const int rowBase = blockIdx.x * 128;
    const int colBase = blockIdx.y * 128;
    const int bz      = blockIdx.z;

    const int r    = tid >> 1;
    const int hf8  = (tid & 1) * 8;
    const int brow = tid >> 4;
    const int bc   = (tid & 15) * 8;
    const int tx   = tid & 15;
    const int ty   = tid >> 4;

    const float* Bp;
    if constexpr (MODE == 0)      Bp = Bmat;
    else if constexpr (MODE == 1) Bp = g_Bz;
    else                          Bp = g_aT + bz * 65536;

    float acc[8][8];
#pragma unroll
    for (int i = 0; i < 8; i++)
#pragma unroll
        for (int j = 0; j < 8; j++) acc[i][j] = 0.f;

    float4 a0, a1, b0, b1;

    auto loadFrag = [&](int k0) {
        if constexpr (MODE == 0) {
            const float* p = g_xT + (rowBase + r) * 256 + k0 + hf8;
            a0 = *(const float4*)p;  a1 = *(const float4*)(p + 4);
        } else if constexpr (MODE == 1) {
            int j  = k0 + hf8;
            int kp = j >> 8;
            int srcrow = rowBase + r + (kp - 3) * 64;
            if (srcrow >= 0 && srcrow < 65536) {
                const float* p = g_xT + srcrow * 256 + (j & 255);
                a0 = *(const float4*)p;  a1 = *(const float4*)(p + 4);
            } else {
                a0 = make_float4(0.f, 0.f, 0.f, 0.f);  a1 = a0;
            }
        } else {
            const float* p = g_Z + ((rowBase + r) * 64 + bz) * 256 + k0 + hf8;
            a0 = *(const float4*)p;  a1 = *(const float4*)(p + 4);
        }
        const float* q = Bp + (k0 + brow) * LDB + colBase + bc;
        b0 = *(const float4*)q;  b1 = *(const float4*)(q + 4);
    };

    auto storeFrag = [&](int buf) {
        As[buf][hf8 + 0][r] = a0.x;  As[buf][hf8 + 1][r] = a0.y;
        As[buf][hf8 + 2][r] = a0.z;  As[buf][hf8 + 3][r] = a0.w;
        As[buf][hf8 + 4][r] = a1.x;  As[buf][hf8 + 5][r] = a1.y;
        As[buf][hf8 + 6][r] = a1.z;  As[buf][hf8 + 7][r] = a1.w;
        *(float4*)&Bs[buf][brow][bc]     = b0;
        *(float4*)&Bs[buf][brow][bc + 4] = b1;
    };

    loadFrag(0);
    storeFrag(0);
    __syncthreads();

    for (int t = 0; t < NT; t++) {
        int cur = t & 1;
        if (t + 1 < NT) loadFrag((t + 1) * 16);

#pragma unroll
        for (int kk = 0; kk < 16; kk++) {
            float4 x0 = *(const float4*)&As[cur][kk][ty * 8];
            float4 x1 = *(const float4*)&As[cur][kk][ty * 8 + 4];
            float4 y0 = *(const float4*)&Bs[cur][kk][tx * 8];
            float4 y1 = *(const float4*)&Bs[cur][kk][tx * 8 + 4];
            float av[8] = {x0.x, x0.y, x0.z, x0.w, x1.x, x1.y, x1.z, x1.w};
            float bw[8] = {y0.x, y0.y, y0.z, y0.w, y1.x, y1.y, y1.z, y1.w};
#pragma unroll
            for (int i = 0; i < 8; i++)
#pragma unroll
                for (int j = 0; j < 8; j++) acc[i][j] += av[i] * bw[j];
        }

        if (t + 1 < NT) storeFrag(cur ^ 1);
        __syncthreads();
    }

    if constexpr (MODE == 0) {
        float* outp = g_xp[dir];
        float4 bb0 = *(const float4*)(bias + colBase + tx * 8);
        float4 bb1 = *(const float4*)(bias + colBase + tx * 8 + 4);
#pragma unroll
        for (int i = 0; i < 8; i++) {
            float* d = outp + (rowBase + ty * 8 + i) * 768 + colBase + tx * 8;
            *(float4*)d       = make_float4(acc[i][0] + bb0.x, acc[i][1] + bb0.y,
                                            acc[i][2] + bb0.z, acc[i][3] + bb0.w);
            *(float4*)(d + 4) = make_float4(acc[i][4] + bb1.x, acc[i][5] + bb1.y,
                                            acc[i][6] + bb1.z, acc[i][7] + bb1.w);
        }
    } else if constexpr (MODE == 1) {
#pragma unroll
        for (int i = 0; i < 8; i++) {
            float* d = g_Z + (rowBase + ty * 8 + i) * 256 + colBase + tx * 8;
            *(float4*)d       = make_float4(acc[i][0], acc[i][1], acc[i][2], acc[i][3]);
            *(float4*)(d + 4) = make_float4(acc[i][4], acc[i][5], acc[i][6], acc[i][7]);
        }
    } else {
        float* outp = g_y + bz * (Sn * 256);
#pragma unroll
        for (int i = 0; i < 8; i++) {
            float* d = outp + (rowBase + ty * 8 + i) * 256 + colBase + tx * 8;
            *(float4*)d       = make_float4(acc[i][0], acc[i][1], acc[i][2], acc[i][3]);
            *(float4*)(d + 4) = make_float4(acc[i][4], acc[i][5], acc[i][6], acc[i][7]);
        }
    }
}

// ---------------------------------------------------------------------------
// persistent GRU v2: 128 blocks = dir(2) x g(4: 16 batches) x cg(16: 16 units).
// Per block: weights for 16 units (48 gate-cols) in smem, stage only this
// batch-group's h (16 KB), island barrier over the 16 blocks of (dir,g).
// ---------------------------------------------------------------------------
static constexpr int GRU_SMEM = (48 * 260 + 16 * 264) * 4;   // 66816 B

__global__ __launch_bounds__(128, 1) void gru_kernel(const float* __restrict__ rec_f,
                                                     const float* __restrict__ rec_b,
                                                     const float* __restrict__ bias_f,
                                                     const float* __restrict__ bias_b)
{
    extern __shared__ float sm[];
    float* Wc = sm;                  // [48][260]  rows j = gate*16+u
    float* hs = sm + 48 * 260;       // [16][264]  this batch-group's h

    const int bid = blockIdx.x;
    const int dir = bid >> 6;            // 0..1
    const int g   = (bid >> 4) & 3;      // batch group, batches g*16..g*16+15
    const int cg  = bid & 15;            // unit group, units cg*16..cg*16+15
    const int isl = bid >> 4;            // island id = dir*4+g (0..7)
    const int tid = threadIdx.x;

    const float* rec  = dir ? rec_b  : rec_f;
    const float* bias = dir ? bias_b : bias_f;
    const float* xp   = g_xp[dir];

    // cache recurrent weight columns: Wc[gate*16+u][c] = rec[c][gate*256+cg*16+u]
    for (int i = tid; i < 48 * 256; i += 128) {
        int c = i / 48, j = i - c * 48;          // j = gate*16+u, u fastest
        int gate = j >> 4, u = j & 15;
        Wc[j * 260 + c] = rec[c * 768 + gate * 256 + cg * 16 + u];
    }

    const int u   = tid >> 3;                // 0..15
    const int bp  = tid & 7;                 // 0..7
    const int lb0 = bp * 2, lb1 = lb0 + 1;   // local batches
    const int gb0 = g * 16 + lb0, gb1 = gb0 + 1;
    const int hu  = cg * 16 + u;             // global hidden unit
    const float bz_ = bias[768 + hu];
    const float br_ = bias[768 + 256 + hu];
    const float bn_ = bias[768 + 512 + hu];

    const float4* wz = (const float4*)&Wc[(0  + u) * 260];
    const float4* wr = (const float4*)&Wc[(16 + u) * 260];
    const float4* wn = (const float4*)&Wc[(32 + u) * 260];

    for (int t = 0; t < 1024; t++) {
        int s = dir ? (1023 - t) : t;
        const float* hrd = g_h[dir][t & 1];
        float*       hwr = g_h[dir][(t & 1) ^ 1];

        // xp loads first: DRAM latency overlaps staging + sync
        int xb0 = (s * 64 + gb0) * 768;
        int xb1 = xb0 + 768;
        float xz0 = xp[xb0 + hu], xr0 = xp[xb0 + 256 + hu], xh0 = xp[xb0 + 512 + hu];
        float xz1 = xp[xb1 + hu], xr1 = xp[xb1 + 256 + hu], xh1 = xp[xb1 + 512 + hu];

        // stage this batch-group's h (16 rows x 256) from L2
        const float4* hrdg = (const float4*)hrd + g * 1024;   // 16 rows * 64 f4
#pragma unroll
        for (int i2 = 0; i2 < 8; i2++) {
            int lin = tid + i2 * 128;          // 0..1023
            int lb = lin >> 6, c4 = lin & 63;
            float4 v = __ldcg(hrdg + lin);
            *(float4*)&hs[lb * 264 + c4 * 4] = v;
        }
        __syncthreads();   // also covers Wc init on t==0

        float az0 = 0, ar0 = 0, an0 = 0, az1 = 0, ar1 = 0, an1 = 0;
        const float4* h0p = (const float4*)&hs[lb0 * 264];
        const float4* h1p = (const float4*)&hs[lb1 * 264];
#pragma unroll 4
        for (int c4 = 0; c4 < 64; c4++) {
            float4 hA = h0p[c4], hB = h1p[c4];
            float4 z4 = wz[c4],  r4 = wr[c4], n4 = wn[c4];
            az0 += hA.x * z4.x + hA.y * z4.y + hA.z * z4.z + hA.w * z4.w;
            ar0 += hA.x * r4.x + hA.y * r4.y + hA.z * r4.z + hA.w * r4.w;
            an0 += hA.x * n4.x + hA.y * n4.y + hA.z * n4.z + hA.w * n4.w;
            az1 += hB.x * z4.x + hB.y * z4.y + hB.z * z4.z + hB.w * z4.w;
            ar1 += hB.x * r4.x + hB.y * r4.y + hB.z * r4.z + hB.w * r4.w;
            an1 += hB.x * n4.x + hB.y * n4.y + hB.z * n4.z + hB.w * n4.w;
        }

        float z0 = 1.f / (1.f + __expf(-(xz0 + az0 + bz_)));
        float r0 = 1.f / (1.f + __expf(-(xr0 + ar0 + br_)));
        float hh0 = tanhf(xh0 + r0 * (an0 + bn_));
        float hp0 = hs[lb0 * 264 + hu];
        float z1 = 1.f / (1.f + __expf(-(xz1 + az1 + bz_)));
        float r1 = 1.f / (1.f + __expf(-(xr1 + ar1 + br_)));
        float hh1 = tanhf(xh1 + r1 * (an1 + bn_));
        float hp1 = hs[lb1 * 264 + hu];

        hwr[gb0 * 256 + hu] = z0 * hp0 + (1.f - z0) * hh0;
        hwr[gb1 * 256 + hu] = z1 * hp1 + (1.f - z1) * hh1;

        // island barrier: only the 16 blocks of (dir,g) synchronize
        __threadfence();
        __syncthreads();
        if (tid == 0) {
            unsigned* ctr = &g_arr2[isl][0];
            atomicAdd(ctr, 1u);
            unsigned target = (unsigned)(t + 1) * 16u;
            while (*((volatile unsigned*)ctr) < target) {}
        }
        __syncthreads();
    }
    // final states in g_h[dir][0]
}

// ---------------------------------------------------------------------------
// aT[b][e][n] = sum_c c[b][c] * Wa[c][n*256+e].  64x64 tiles, grid(1024).
// ---------------------------------------------------------------------------
__global__ __launch_bounds__(256) void hyperAT_kernel(const float* __restrict__ Wa)
{
    __shared__ float As[16][68];
    __shared__ float Bs[16][64];
    const int tid = threadIdx.x;
    const int colBase = blockIdx.x * 64;
    const int bb = tid & 63, cg = tid >> 6;
    const int brow = tid >> 4, bc = (tid & 15) * 4;
    const int tx = tid & 15, ty = tid >> 4;

    float acc[4][4];
#pragma unroll
    for (int i = 0; i < 4; i++)
#pragma unroll
        for (int j = 0; j < 4; j++) acc[i][j] = 0.f;

    for (int k0 = 0; k0 < 512; k0 += 16) {
        int j0 = k0 + cg * 4;
        const float* src = (j0 < 256) ? (g_h[0][0] + bb * 256 + j0)
                                      : (g_h[1][0] + bb * 256 + (j0 - 256));
        float4 v  = *(const float4*)src;
        float4 bv = *(const float4*)(Wa + (k0 + brow) * 65536 + colBase + bc);

        __syncthreads();
        As[cg * 4 + 0][bb] = v.x;  As[cg * 4 + 1][bb] = v.y;
        As[cg * 4 + 2][bb] = v.z;  As[cg * 4 + 3][bb] = v.w;
        *(float4*)&Bs[brow][bc] = bv;
        __syncthreads();

#pragma unroll
        for (int kk = 0; kk < 16; kk++) {
            float4 a4 = *(const float4*)&As[kk][ty * 4];
            float4 b4 = *(const float4*)&Bs[kk][tx * 4];
            float av[4] = {a4.x, a4.y, a4.z, a4.w};
            float bw[4] = {b4.x, b4.y, b4.z, b4.w};
#pragma unroll
            for (int i = 0; i < 4; i++)
#pragma unroll
                for (int j = 0; j < 4; j++) acc[i][j] += av[i] * bw[j];
        }
    }
#pragma unroll
    for (int j = 0; j < 4; j++) {
        int jc = colBase + tx * 4 + j;
        int n = jc >> 8, e = jc & 255;
#pragma unroll
        for (int i = 0; i < 4; i++)
            g_aT[(ty * 4 + i) * 65536 + e * 256 + n] = acc[i][j];
    }
}

// ---------------------------------------------------------------------------
__global__ void pool_kernel(float* __restrict__ out, const float* __restrict__ bias)
{
    int n = threadIdx.x;
    int p = blockIdx.x;
    int b = blockIdx.y;
    const float* y = g_y + ((b * Sn) + p * 3) * 256 + n;
    float v = fmaxf(fmaxf(y[0], y[256]), y[512]) + bias[n];
    out[(b * 341 + p) * 256 + n] = fmaxf(v, 0.f);
}

// ---------------------------------------------------------------------------
extern "C" void kernel_launch(void* const* d_in, const int* in_sizes, int n_in,
                              void* d_out, int out_size)
{
    (void)in_sizes; (void)n_in; (void)out_size;
    const float* x     = (const float*)d_in[0];
    const float* gk_f  = (const float*)d_in[2];
    const float* gr_f  = (const float*)d_in[3];
    const float* gb_f  = (const float*)d_in[4];
    const float* gk_b  = (const float*)d_in[5];
    const float* gr_b  = (const float*)d_in[6];
    const float* gb_b  = (const float*)d_in[7];
    const float* Wa    = (const float*)d_in[8];
    const float* Wb    = (const float*)d_in[9];
    const float* cbias = (const float*)d_in[10];
    float* out = (float*)d_out;

    cudaFuncSetAttribute(gru_kernel, cudaFuncAttributeMaxDynamicSharedMemorySize,
                         GRU_SMEM);

    transpose_kernel<<<dim3(1024, 64), 64>>>(x);
    reset_kernel<<<256, 256>>>();
    gemm128<0><<<dim3(512, 6, 1), 256>>>(gk_f, gb_f, 0);
    gemm128<0><<<dim3(512, 6, 1), 256>>>(gk_b, gb_b, 1);
    gru_kernel<<<128, 128, GRU_SMEM>>>(gr_f, gr_b, gb_f, gb_b);
    prep_bz_kernel<<<1792, 256>>>(Wb);
    gemm128<1><<<dim3(512, 2, 1), 256>>>(nullptr, nullptr, 0);
    hyperAT_kernel<<<1024, 256>>>(Wa);
    gemm128<2><<<dim3(8, 2, 64), 256>>>(nullptr, nullptr, 0);
    pool_kernel<<<dim3(341, 64), 256>>>(out, cbias);
}

// round 11
// speedup vs baseline: 1.1084x; 1.1084x over previous
#include <cuda_runtime.h>

// ---------------------------------------------------------------------------
// B=64, S=1024, H=256, NF=C=256, K=7, POOL=3, layer==1 (no pad).
// Inputs: 0 x[64,1024,256] 1 layer 2 gk_f[256,768] 3 gr_f[256,768] 4 gb_f[2,768]
//         5 gk_b 6 gr_b 7 gb_b 8 Wa[512,65536] 9 Wb[256,1792] 10 conv_bias[256]
// Output: [64, 341, 256] f32
//
// Conv restructured:  y[b][s][n] = sum_e a[b][n][e] * Z[b][s][e],
//   Z[b][s][e] = sum_{k,m} x[b][s+k-3][m] * Wb[e][m*7+k]   (static conv)
// GEMMs use packed fp32 FFMA2 (fma.rn.f32x2) — 2x fp32 FMA issue width,
// bit-identical IEEE fp32 rounding.
// GRU: reverted to the measured-best R8 version (global 128-block barrier).
// ---------------------------------------------------------------------------

static constexpr int Bn = 64, Sn = 1024, Hn = 256, NFn = 256, Kn = 7;

// -------------------- static device scratch --------------------------------
__device__ float    g_xT[Sn * Bn * 256];          //  67 MB  [s][b][c]
__device__ float    g_xp[2][Sn * Bn * 768];       // 403 MB  [dir][s*64+b][768]
__device__ float    g_h[2][2][Bn * Hn];           //         [dir][pp][b][h]
__device__ float    g_Bz[Kn * 256 * 256];         // 1.8 MB  [k*256+m][e]
__device__ float    g_Z[Sn * Bn * 256];           //  67 MB  [s*64+b][e]
__device__ float    g_aT[Bn * 256 * 256];         //  17 MB  [b][e][n]
__device__ float    g_y[Bn * Sn * NFn];           //  67 MB  [b][s][n]
__device__ unsigned g_arrive;

// ---------------------------------------------------------------------------
__global__ void transpose_kernel(const float* __restrict__ x)
{
    int s = blockIdx.x, b = blockIdx.y;
    int c4 = threadIdx.x;
    float4 v = ((const float4*)(x + (b * Sn + s) * 256))[c4];
    ((float4*)(g_xT + (s * Bn + b) * 256))[c4] = v;
}

// ---------------------------------------------------------------------------
// reset barrier counter + zero h state (every launch -> graph-replay safe)
// ---------------------------------------------------------------------------
__global__ void reset_kernel()
{
    int i = blockIdx.x * blockDim.x + threadIdx.x;
    if (i == 0) g_arrive = 0u;
    ((float*)g_h)[i] = 0.f;                       // 2*2*64*256 = 65536
}

// ---------------------------------------------------------------------------
// Bz[(k*256+m)][e] = Wb[e][m*7+k]
// ---------------------------------------------------------------------------
__global__ void prep_bz_kernel(const float* __restrict__ Wb)
{
    int j = blockIdx.x;                 // 0..1791
    int e = threadIdx.x;                // 0..255
    int k = j >> 8, m = j & 255;
    g_Bz[j * 256 + e] = Wb[e * 1792 + m * 7 + k];
}

// ---------------------------------------------------------------------------
// packed fp32 helpers (SASS FFMA2) — identical IEEE fp32 rounding
// ---------------------------------------------------------------------------
__device__ __forceinline__ unsigned long long pack2(float lo, float hi) {
    unsigned long long r;
    asm("mov.b64 %0, {%1, %2};" : "=l"(r) : "f"(lo), "f"(hi));
    return r;
}
__device__ __forceinline__ unsigned long long pack2dup(float v) {
    unsigned long long r;
    asm("mov.b64 %0, {%1, %1};" : "=l"(r) : "f"(v));
    return r;
}
__device__ __forceinline__ void fma2(unsigned long long& acc,
                                     unsigned long long a, unsigned long long b) {
    asm("fma.rn.f32x2 %0, %1, %2, %0;" : "+l"(acc) : "l"(a), "l"(b));
}
__device__ __forceinline__ float2 unpack2(unsigned long long v) {
    float lo, hi;
    asm("mov.b64 {%0, %1}, %2;" : "=f"(lo), "=f"(hi) : "l"(v));
    return make_float2(lo, hi);
}

// ---------------------------------------------------------------------------
// 128x128-tile SGEMM, 256 threads, 8x8/thread, BK=16, double-buffered smem,
// FFMA2 inner loop (acc packed along j-pairs).
// MODE 0: xp = xT @ Wk + bias.   K=256, LDB=768. grid(512,6)
// MODE 1: Z = im2col(xT) @ Bz.   K=1792, LDB=256. grid(512,2)
// MODE 2: y[b] = Z[:,b,:] @ aT[b]. K=256, LDB=256. grid(8,2,64)
// ---------------------------------------------------------------------------
template <int MODE>
__global__ __launch_bounds__(256, 2) void gemm128(const float* __restrict__ Bmat,
                                                  const float* __restrict__ bias,
                                                  int dir)
{
    constexpr int KDIM = (MODE == 1) ? 1792 : 256;
    constexpr int LDB  = (MODE == 0) ? 768 : 256;
    constexpr int NT   = KDIM / 16;

    __shared__ float As[2][16][132];
    __shared__ float Bs[2][16][128];

    const int tid     = threadIdx.x;
    const int rowBase = blockIdx.x * 128;
    const int colBase = blockIdx.y * 128;
    const int bz      = blockIdx.z;

    const int r    = tid >> 1;
    const int hf8  = (tid & 1) * 8;
    const int brow = tid >> 4;
    const int bc   = (tid & 15) * 8;
    const int tx   = tid & 15;
    const int ty   = tid >> 4;

    const float* Bp;
    if constexpr (MODE == 0)      Bp = Bmat;
    else if constexpr (MODE == 1) Bp = g_Bz;
    else                          Bp = g_aT + bz * 65536;

    unsigned long long acc2[8][4];   // [i][j2] = (acc[i][2j2], acc[i][2j2+1])
#pragma unroll
    for (int i = 0; i < 8; i++)
#pragma unroll
        for (int j = 0; j < 4; j++) acc2[i][j] = 0ull;

    float4 a0, a1, b0, b1;

    auto loadFrag = [&](int k0) {
        if constexpr (MODE == 0) {
            const float* p = g_xT + (rowBase + r) * 256 + k0 + hf8;
            a0 = *(const float4*)p;  a1 = *(const float4*)(p + 4);
        } else if constexpr (MODE == 1) {
            int j  = k0 + hf8;
            int kp = j >> 8;
            int srcrow = rowBase + r + (kp - 3) * 64;
            if (srcrow >= 0 && srcrow < 65536) {
                const float* p = g_xT + srcrow * 256 + (j & 255);
                a0 = *(const float4*)p;  a1 = *(const float4*)(p + 4);
            } else {
                a0 = make_float4(0.f, 0.f, 0.f, 0.f);  a1 = a0;
            }
        } else {
            const float* p = g_Z + ((rowBase + r) * 64 + bz) * 256 + k0 + hf8;
            a0 = *(const float4*)p;  a1 = *(const float4*)(p + 4);
        }
        const float* q = Bp + (k0 + brow) * LDB + colBase + bc;
        b0 = *(const float4*)q;  b1 = *(const float4*)(q + 4);
    };

    auto storeFrag = [&](int buf) {
        As[buf][hf8 + 0][r] = a0.x;  As[buf][hf8 + 1][r] = a0.y;
        As[buf][hf8 + 2][r] = a0.z;  As[buf][hf8 + 3][r] = a0.w;
        As[buf][hf8 + 4][r] = a1.x;  As[buf][hf8 + 5][r] = a1.y;
        As[buf][hf8 + 6][r] = a1.z;  As[buf][hf8 + 7][r] = a1.w;
        *(float4*)&Bs[buf][brow][bc]     = b0;
        *(float4*)&Bs[buf][brow][bc + 4] = b1;
    };

    loadFrag(0);
    storeFrag(0);
    __syncthreads();

    for (int t = 0; t < NT; t++) {
        int cur = t & 1;
        if (t + 1 < NT) loadFrag((t + 1) * 16);

#pragma unroll
        for (int kk = 0; kk < 16; kk++) {
            float4 x0 = *(const float4*)&As[cur][kk][ty * 8];
            float4 x1 = *(const float4*)&As[cur][kk][ty * 8 + 4];
            float4 y0 = *(const float4*)&Bs[cur][kk][tx * 8];
            float4 y1 = *(const float4*)&Bs[cur][kk][tx * 8 + 4];
            float av[8] = {x0.x, x0.y, x0.z, x0.w, x1.x, x1.y, x1.z, x1.w};
            unsigned long long bw2[4];
            bw2[0] = pack2(y0.x, y0.y);  bw2[1] = pack2(y0.z, y0.w);
            bw2[2] = pack2(y1.x, y1.y);  bw2[3] = pack2(y1.z, y1.w);
#pragma unroll
            for (int i = 0; i < 8; i++) {
                unsigned long long av2 = pack2dup(av[i]);
#pragma unroll
                for (int j = 0; j < 4; j++) fma2(acc2[i][j], av2, bw2[j]);
            }
        }

        if (t + 1 < NT) storeFrag(cur ^ 1);
        __syncthreads();
    }

    // ---- epilogue ----------------------------------------------------------
    if constexpr (MODE == 0) {
        float* outp = g_xp[dir];
        float4 bb0 = *(const float4*)(bias + colBase + tx * 8);
        float4 bb1 = *(const float4*)(bias + colBase + tx * 8 + 4);
#pragma unroll
        for (int i = 0; i < 8; i++) {
            float2 c0 = unpack2(acc2[i][0]), c1 = unpack2(acc2[i][1]);
            float2 c2 = unpack2(acc2[i][2]), c3 = unpack2(acc2[i][3]);
            float* d = outp + (rowBase + ty * 8 + i) * 768 + colBase + tx * 8;
            *(float4*)d       = make_float4(c0.x + bb0.x, c0.y + bb0.y,
                                            c1.x + bb0.z, c1.y + bb0.w);
            *(float4*)(d + 4) = make_float4(c2.x + bb1.x, c2.y + bb1.y,
                                            c3.x + bb1.z, c3.y + bb1.w);
        }
    } else if constexpr (MODE == 1) {
#pragma unroll
        for (int i = 0; i < 8; i++) {
            float2 c0 = unpack2(acc2[i][0]), c1 = unpack2(acc2[i][1]);
            float2 c2 = unpack2(acc2[i][2]), c3 = unpack2(acc2[i][3]);
            float* d = g_Z + (rowBase + ty * 8 + i) * 256 + colBase + tx * 8;
            *(float4*)d       = make_float4(c0.x, c0.y, c1.x, c1.y);
            *(float4*)(d + 4) = make_float4(c2.x, c2.y, c3.x, c3.y);
        }
    } else {
        float* outp = g_y + bz * (Sn * 256);
#pragma unroll
        for (int i = 0; i < 8; i++) {
            float2 c0 = unpack2(acc2[i][0]), c1 = unpack2(acc2[i][1]);
            float2 c2 = unpack2(acc2[i][2]), c3 = unpack2(acc2[i][3]);
            float* d = outp + (rowBase + ty * 8 + i) * 256 + colBase + tx * 8;
            *(float4*)d       = make_float4(c0.x, c0.y, c1.x, c1.y);
            *(float4*)(d + 4) = make_float4(c2.x, c2.y, c3.x, c3.y);
        }
    }
}

// ---------------------------------------------------------------------------
// persistent GRU, both directions — EXACT R8 version (measured best).
// 128 blocks x 128 threads; block = (dir, 4 hidden units); global barrier.
// ---------------------------------------------------------------------------
static constexpr int GRU_SMEM = (64 * 264 + 12 * 260) * 4;   // 80064 B

__global__ __launch_bounds__(128, 1) void gru_kernel(const float* __restrict__ rec_f,
                                                     const float* __restrict__ rec_b,
                                                     const float* __restrict__ bias_f,
                                                     const float* __restrict__ bias_b)
{
    extern __shared__ float sm[];
    float* hs = sm;                 // [64][264]
    float* Wc = sm + 64 * 264;      // [12][260]

    const int bid = blockIdx.x;
    const int dir = bid >> 6;
    const int cb  = bid & 63;
    const int u0  = cb * 4;
    const int tid = threadIdx.x;

    const float* rec  = dir ? rec_b  : rec_f;
    const float* bias = dir ? bias_b : bias_f;
    const float* xp   = g_xp[dir];

    for (int i = tid; i < 12 * 256; i += 128) {
        int c = i & 255, j = i >> 8;
        int g = j >> 2,  u = j & 3;
        Wc[j * 260 + c] = rec[c * 768 + g * 256 + u0 + u];
    }

    const int u  = tid & 3;
    const int rg = tid >> 2;
    const int b0 = rg * 2, b1 = b0 + 1;
    const int hu = u0 + u;
    const float bz_ = bias[768 + hu];
    const float br_ = bias[768 + 256 + hu];
    const float bn_ = bias[768 + 512 + hu];

    const float4* wz = (const float4*)&Wc[(0 * 4 + u) * 260];
    const float4* wr = (const float4*)&Wc[(1 * 4 + u) * 260];
    const float4* wn = (const float4*)&Wc[(2 * 4 + u) * 260];

    for (int t = 0; t < 1024; t++) {
        int s = dir ? (1023 - t) : t;
        const float* hrd = g_h[dir][t & 1];
        float*       hwr = g_h[dir][(t & 1) ^ 1];

#pragma unroll 8
        for (int i = 0; i < 32; i++) {
            int lin = tid + i * 128;
            int b = lin >> 6, c4 = lin & 63;
            float4 v = __ldcg((const float4*)hrd + lin);
            *(float4*)&hs[b * 264 + c4 * 4] = v;
        }
        __syncthreads();

        int xb0 = (s * 64 + b0) * 768;
        int xb1 = xb0 + 768;
        float xz0 = xp[xb0 + hu], xr0 = xp[xb0 + 256 + hu], xh0 = xp[xb0 + 512 + hu];
        float xz1 = xp[xb1 + hu], xr1 = xp[xb1 + 256 + hu], xh1 = xp[xb1 + 512 + hu];

        float az0 = 0, ar0 = 0, an0 = 0, az1 = 0, ar1 = 0, an1 = 0;
        const float4* h0p = (const float4*)&hs[b0 * 264];
        const float4* h1p = (const float4*)&hs[b1 * 264];
#pragma unroll 4
        for (int c4 = 0; c4 < 64; c4++) {
            float4 hA = h0p[c4], hB = h1p[c4];
            float4 z4 = wz[c4],  r4 = wr[c4], n4 = wn[c4];
            az0 += hA.x * z4.x + hA.y * z4.y + hA.z * z4.z + hA.w * z4.w;
            ar0 += hA.x * r4.x + hA.y * r4.y + hA.z * r4.z + hA.w * r4.w;
            an0 += hA.x * n4.x + hA.y * n4.y + hA.z * n4.z + hA.w * n4.w;
            az1 += hB.x * z4.x + hB.y * z4.y + hB.z * z4.z + hB.w * z4.w;
            ar1 += hB.x * r4.x + hB.y * r4.y + hB.z * r4.z + hB.w * r4.w;
            an1 += hB.x * n4.x + hB.y * n4.y + hB.z * n4.z + hB.w * n4.w;
        }

        float z0 = 1.f / (1.f + __expf(-(xz0 + az0 + bz_)));
        float r0 = 1.f / (1.f + __expf(-(xr0 + ar0 + br_)));
        float hh0 = tanhf(xh0 + r0 * (an0 + bn_));
        float hp0 = hs[b0 * 264 + hu];
        float z1 = 1.f / (1.f + __expf(-(xz1 + az1 + bz_)));
        float r1 = 1.f / (1.f + __expf(-(xr1 + ar1 + br_)));
        float hh1 = tanhf(xh1 + r1 * (an1 + bn_));
        float hp1 = hs[b1 * 264 + hu];

        hwr[b0 * 256 + hu] = z0 * hp0 + (1.f - z0) * hh0;
        hwr[b1 * 256 + hu] = z1 * hp1 + (1.f - z1) * hh1;

        __threadfence();
        __syncthreads();
        if (tid == 0) {
            atomicAdd(&g_arrive, 1u);
            unsigned target = (unsigned)(t + 1) * 128u;
            while (*((volatile unsigned*)&g_arrive) < target) {}
        }
        __syncthreads();
    }
    // final states in g_h[dir][0]
}

// ---------------------------------------------------------------------------
// aT[b][e][n] = sum_c c[b][c] * Wa[c][n*256+e].  64x64 tiles, grid(1024).
// ---------------------------------------------------------------------------
__global__ __launch_bounds__(256) void hyperAT_kernel(const float* __restrict__ Wa)
{
    __shared__ float As[16][68];
    __shared__ float Bs[16][64];
    const int tid = threadIdx.x;
    const int colBase = blockIdx.x * 64;
    const int bb = tid & 63, cg = tid >> 6;
    const int brow = tid >> 4, bc = (tid & 15) * 4;
    const int tx = tid & 15, ty = tid >> 4;

    float acc[4][4];
#pragma unroll
    for (int i = 0; i < 4; i++)
#pragma unroll
        for (int j = 0; j < 4; j++) acc[i][j] = 0.f;

    for (int k0 = 0; k0 < 512; k0 += 16) {
        int j0 = k0 + cg * 4;
        const float* src = (j0 < 256) ? (g_h[0][0] + bb * 256 + j0)
                                      : (g_h[1][0] + bb * 256 + (j0 - 256));
        float4 v  = *(const float4*)src;
        float4 bv = *(const float4*)(Wa + (k0 + brow) * 65536 + colBase + bc);

        __syncthreads();
        As[cg * 4 + 0][bb] = v.x;  As[cg * 4 + 1][bb] = v.y;
        As[cg * 4 + 2][bb] = v.z;  As[cg * 4 + 3][bb] = v.w;
        *(float4*)&Bs[brow][bc] = bv;
        __syncthreads();

#pragma unroll
        for (int kk = 0; kk < 16; kk++) {
            float4 a4 = *(const float4*)&As[kk][ty * 4];
            float4 b4 = *(const float4*)&Bs[kk][tx * 4];
            float av[4] = {a4.x, a4.y, a4.z, a4.w};
            float bw[4] = {b4.x, b4.y, b4.z, b4.w};
#pragma unroll
            for (int i = 0; i < 4; i++)
#pragma unroll
                for (int j = 0; j < 4; j++) acc[i][j] += av[i] * bw[j];
        }
    }
#pragma unroll
    for (int j = 0; j < 4; j++) {
        int jc = colBase + tx * 4 + j;
        int n = jc >> 8, e = jc & 255;
#pragma unroll
        for (int i = 0; i < 4; i++)
            g_aT[(ty * 4 + i) * 65536 + e * 256 + n] = acc[i][j];
    }
}

// ---------------------------------------------------------------------------
__global__ void pool_kernel(float* __restrict__ out, const float* __restrict__ bias)
{
    int n = threadIdx.x;
    int p = blockIdx.x;
    int b = blockIdx.y;
    const float* y = g_y + ((b * Sn) + p * 3) * 256 + n;
    float v = fmaxf(fmaxf(y[0], y[256]), y[512]) + bias[n];
    out[(b * 341 + p) * 256 + n] = fmaxf(v, 0.f);
}

// ---------------------------------------------------------------------------
extern "C" void kernel_launch(void* const* d_in, const int* in_sizes, int n_in,
                              void* d_out, int out_size)
{
    (void)in_sizes; (void)n_in; (void)out_size;
    const float* x     = (const float*)d_in[0];
    const float* gk_f  = (const float*)d_in[2];
    const float* gr_f  = (const float*)d_in[3];
    const float* gb_f  = (const float*)d_in[4];
    const float* gk_b  = (const float*)d_in[5];
    const float* gr_b  = (const float*)d_in[6];
    const float* gb_b  = (const float*)d_in[7];
    const float* Wa    = (const float*)d_in[8];
    const float* Wb    = (const float*)d_in[9];
    const float* cbias = (const float*)d_in[10];
    float* out = (float*)d_out;

    cudaFuncSetAttribute(gru_kernel, cudaFuncAttributeMaxDynamicSharedMemorySize,
                         GRU_SMEM);

    transpose_kernel<<<dim3(1024, 64), 64>>>(x);
    reset_kernel<<<256, 256>>>();
    gemm128<0><<<dim3(512, 6, 1), 256>>>(gk_f, gb_f, 0);
    gemm128<0><<<dim3(512, 6, 1), 256>>>(gk_b, gb_b, 1);
    gru_kernel<<<128, 128, GRU_SMEM>>>(gr_f, gr_b, gb_f, gb_b);
    prep_bz_kernel<<<1792, 256>>>(Wb);
    gemm128<1><<<dim3(512, 2, 1), 256>>>(nullptr, nullptr, 0);
    hyperAT_kernel<<<1024, 256>>>(Wa);
    gemm128<2><<<dim3(8, 2, 64), 256>>>(nullptr, nullptr, 0);
    pool_kernel<<<dim3(341, 64), 256>>>(out, cbias);
}